// round 1
// baseline (speedup 1.0000x reference)
#include <cuda_runtime.h>

// Problem constants
#define NB     8192   // batch
#define NM     50     // members per group
#define ND     64     // embedding dim

// ---- shared memory layout (in floats) -------------------------------------
constexpr int OFF_ME   = 0;            // 50x64 gathered member embeddings
constexpr int OFF_H1   = 3200;         // 50x64 relu(me@W1+b1)
constexpr int OFF_W1   = 6400;         // 64x64 ue_W1
constexpr int OFF_W2   = 10496;        // 64x64 ue_W2
constexpr int OFF_ATW1 = 14592;        // 128x16 at_W1
constexpr int OFF_HAT  = 16640;        // 50x16 relu(attention hidden)
constexpr int OFF_IT   = 17440;        // 64 item embedding
constexpr int OFF_B1   = 17504;        // 64 ue_b1
constexpr int OFF_B2   = 17568;        // 64 ue_b2
constexpr int OFF_ATW2 = 17632;        // 16 at_W2
constexpr int OFF_C    = 17648;        // 16 item-side attention bias
constexpr int OFF_HBAR = 17664;        // 64 mean_m relu(h1)
constexpr int OFF_UAGG = 17728;        // 64 user_agg
constexpr int OFF_LOG  = 17792;        // 64 logits (50 used)
constexpr int OFF_WSM  = 17856;        // 64 softmax weights (50 used)
constexpr int OFF_G    = 17920;        // 64 g = g_att + ge
constexpr int OFF_GE   = 17984;        // 64 group embedding row
constexpr int OFF_Z    = 18048;        // 96 relu(user_agg@ge_W1+b1)
constexpr int OFF_HPR  = 18144;        // 16 (8 used) pred hidden
constexpr int OFF_RED  = 18160;        // 64 reduction scratch
constexpr int OFF_MEM  = 18224;        // 64 (ints) member ids
constexpr int SMEM_FLOATS = 18288;
constexpr int SMEM_BYTES  = SMEM_FLOATS * 4;   // 73152 B -> 3 CTAs/SM

__device__ float g_dkl_partial[NB];

extern "C" __global__ void __launch_bounds__(256)
agree_kernel(
    const int*   __restrict__ group_inputs,
    const int*   __restrict__ item_inputs,
    const int*   __restrict__ group_members,
    const float* __restrict__ user_emb,
    const float* __restrict__ item_emb,
    const float* __restrict__ group_emb,
    const float* __restrict__ ue_W1, const float* __restrict__ ue_b1,
    const float* __restrict__ ue_W2, const float* __restrict__ ue_b2,
    const float* __restrict__ ge_W1, const float* __restrict__ ge_b1,
    const float* __restrict__ ge_W2, const float* __restrict__ ge_b2,
    const float* __restrict__ at_W1, const float* __restrict__ at_b1,
    const float* __restrict__ at_W2, const float* __restrict__ at_b2,
    const float* __restrict__ pr_W1, const float* __restrict__ pr_b1,
    const float* __restrict__ pr_W2, const float* __restrict__ pr_b2,
    float* __restrict__ y_out)
{
    extern __shared__ float sm[];
    const int tid = threadIdx.x;
    const int bid = blockIdx.x;

    const int gidx = group_inputs[bid];
    const int iidx = item_inputs[bid];
    int* mem_s = (int*)(sm + OFF_MEM);

    // ---------------- Phase L: stage inputs into SMEM ----------------
    if (tid < NM) mem_s[tid] = group_members[gidx * NM + tid];
    if (tid < ND) {
        sm[OFF_IT + tid] = item_emb[iidx * ND + tid];
        sm[OFF_B1 + tid] = ue_b1[tid];
        sm[OFF_B2 + tid] = ue_b2[tid];
        sm[OFF_GE + tid] = group_emb[gidx * ND + tid];
    }
    if (tid < 16) sm[OFF_ATW2 + tid] = at_W2[tid];
    {
        float4*       w1d = (float4*)(sm + OFF_W1);
        float4*       w2d = (float4*)(sm + OFF_W2);
        const float4* w1g = (const float4*)ue_W1;
        const float4* w2g = (const float4*)ue_W2;
        for (int i = tid; i < 1024; i += 256) { w1d[i] = w1g[i]; w2d[i] = w2g[i]; }
        float4*       awd = (float4*)(sm + OFF_ATW1);
        const float4* awg = (const float4*)at_W1;
        for (int i = tid; i < 512; i += 256) awd[i] = awg[i];
    }
    __syncthreads();

    // gather me = user_emb[members]  (50 rows x 16 float4)
    {
        float4*       med = (float4*)(sm + OFF_ME);
        const float4* ueg = (const float4*)user_emb;
        for (int i = tid; i < NM * 16; i += 256) {
            int row = i >> 4, c4 = i & 15;
            med[i] = ueg[mem_s[row] * 16 + c4];
        }
    }
    __syncthreads();

    // ---------------- Phase 1: h1 = relu(me @ ue_W1 + b1)  (50x64) ----------
    // 256 threads: mg = tid/32 (8 row groups), j0 = (tid%32)*2 (2 cols each).
    // Rows m = mg + 8r, r=0..5 always valid (<=47); r=6 (48+mg) valid iff mg<2
    // -> warp-uniform predicate, exactly 50 rows of work, zero waste.
    {
        const int mg = tid >> 5;
        const int j0 = (tid & 31) * 2;
        const bool full = (mg < 2);
        float acc[7][2];
        #pragma unroll
        for (int r = 0; r < 7; r++) { acc[r][0] = sm[OFF_B1 + j0]; acc[r][1] = sm[OFF_B1 + j0 + 1]; }
        #pragma unroll 8
        for (int k = 0; k < ND; k++) {
            float2 wv = *(const float2*)&sm[OFF_W1 + k * ND + j0];
            #pragma unroll
            for (int r = 0; r < 6; r++) {
                float a = sm[OFF_ME + (mg + 8 * r) * ND + k];   // warp-broadcast
                acc[r][0] += a * wv.x; acc[r][1] += a * wv.y;
            }
            if (full) {
                float a = sm[OFF_ME + (mg + 48) * ND + k];
                acc[6][0] += a * wv.x; acc[6][1] += a * wv.y;
            }
        }
        #pragma unroll
        for (int r = 0; r < 6; r++) {
            int m = mg + 8 * r;
            sm[OFF_H1 + m * ND + j0]     = fmaxf(acc[r][0], 0.f);
            sm[OFF_H1 + m * ND + j0 + 1] = fmaxf(acc[r][1], 0.f);
        }
        if (full) {
            int m = mg + 48;
            sm[OFF_H1 + m * ND + j0]     = fmaxf(acc[6][0], 0.f);
            sm[OFF_H1 + m * ND + j0 + 1] = fmaxf(acc[6][1], 0.f);
        }
    }
    __syncthreads();

    // ---------------- Phase 2: hbar = mean_m relu(h1)   +   c[j] ------------
    if (tid < ND) {
        float s = 0.f;
        #pragma unroll 10
        for (int m = 0; m < NM; m++) s += sm[OFF_H1 + m * ND + tid];
        sm[OFF_HBAR + tid] = s * (1.0f / (float)NM);
    } else if (tid < ND + 16) {
        int j = tid - ND;
        float s = at_b1[j];
        #pragma unroll 8
        for (int k = 0; k < ND; k++) s += sm[OFF_IT + k] * sm[OFF_ATW1 + (ND + k) * 16 + j];
        sm[OFF_C + j] = s;
    }
    __syncthreads();

    // ---------------- Phase 3: attention hidden (50x16) ---------------------
    {
        const int grp = tid >> 4;     // 0..15
        const int j   = tid & 15;
        const bool full = (grp < 2);  // row 48+grp valid iff grp<2 (warp 0)
        float acc[4];
        #pragma unroll
        for (int r = 0; r < 4; r++) acc[r] = sm[OFF_C + j];
        #pragma unroll 8
        for (int k = 0; k < ND; k++) {
            float w = sm[OFF_ATW1 + k * 16 + j];
            #pragma unroll
            for (int r = 0; r < 3; r++)
                acc[r] += sm[OFF_ME + (grp + 16 * r) * ND + k] * w;
            if (full) acc[3] += sm[OFF_ME + (grp + 48) * ND + k] * w;
        }
        #pragma unroll
        for (int r = 0; r < 3; r++)
            sm[OFF_HAT + (grp + 16 * r) * 16 + j] = fmaxf(acc[r], 0.f);
        if (full) sm[OFF_HAT + (grp + 48) * 16 + j] = fmaxf(acc[3], 0.f);
    }
    __syncthreads();

    // ---------------- Phase 4: user_agg  +  logits ---------------------------
    if (tid < ND) {
        float s = sm[OFF_B2 + tid];
        #pragma unroll 8
        for (int k = 0; k < ND; k++) s += sm[OFF_HBAR + k] * sm[OFF_W2 + k * ND + tid];
        sm[OFF_UAGG + tid] = fmaxf(s, 0.f);
    } else if (tid < ND + NM) {
        int m = tid - ND;
        float s = at_b2[0];
        #pragma unroll
        for (int j = 0; j < 16; j++) s += sm[OFF_HAT + m * 16 + j] * sm[OFF_ATW2 + j];
        sm[OFF_LOG + m] = s;
    }
    __syncthreads();

    // ---------------- Phase 5: softmax over 50 ------------------------------
    {
        float v = (tid < NM) ? sm[OFF_LOG + tid] : -3.0e38f;
        if (tid < 64) {
            #pragma unroll
            for (int o = 16; o > 0; o >>= 1) v = fmaxf(v, __shfl_xor_sync(0xffffffff, v, o));
            if ((tid & 31) == 0) sm[OFF_RED + (tid >> 5)] = v;
        }
        __syncthreads();
        float mx = fmaxf(sm[OFF_RED + 0], sm[OFF_RED + 1]);
        float e = 0.f;
        if (tid < NM) { e = __expf(sm[OFF_LOG + tid] - mx); sm[OFF_WSM + tid] = e; }
        float sv = (tid < NM) ? e : 0.f;
        if (tid < 64) {
            #pragma unroll
            for (int o = 16; o > 0; o >>= 1) sv += __shfl_xor_sync(0xffffffff, sv, o);
            if ((tid & 31) == 0) sm[OFF_RED + 2 + (tid >> 5)] = sv;
        }
        __syncthreads();
        float inv = 1.0f / (sm[OFF_RED + 2] + sm[OFF_RED + 3]);
        if (tid < NM) sm[OFF_WSM + tid] *= inv;
    }
    __syncthreads();

    // ---------------- Phase 6: g = attn-pool + ge   ;   z = relu(uagg@geW1+b)
    if (tid < ND) {
        float s = 0.f;
        #pragma unroll 10
        for (int m = 0; m < NM; m++) s += sm[OFF_WSM + m] * sm[OFF_ME + m * ND + tid];
        sm[OFF_G + tid] = s + sm[OFF_GE + tid];
    } else if (tid < ND + 96) {
        int j = tid - ND;
        float s = ge_b1[j];
        #pragma unroll 8
        for (int k = 0; k < ND; k++) s += sm[OFF_UAGG + k] * __ldg(&ge_W1[k * 96 + j]);
        sm[OFF_Z + j] = fmaxf(s, 0.f);
    }
    __syncthreads();

    // ---------------- Phase 7: dkl partial  +  pred hidden -------------------
    if (tid < ND) {
        float s = ge_b2[tid];   // only first 64 cols of ge_W2 needed (gz[:, :d])
        #pragma unroll 8
        for (int k = 0; k < 96; k++) s += sm[OFF_Z + k] * __ldg(&ge_W2[k * 128 + tid]);
        float diff = sm[OFF_GE + tid] - s;
        float p = diff * diff;
        #pragma unroll
        for (int o = 16; o > 0; o >>= 1) p += __shfl_xor_sync(0xffffffff, p, o);
        if ((tid & 31) == 0) sm[OFF_RED + 8 + (tid >> 5)] = p;
    } else if (tid < ND + 8) {
        int j = tid - ND;
        float s = pr_b1[j];
        const float* gv = sm + OFF_G;
        const float* iv = sm + OFF_IT;
        #pragma unroll 8
        for (int k = 0; k < ND; k++) {
            float gk = gv[k], ik = iv[k];
            s += (gk * ik) * __ldg(&pr_W1[k * 8 + j]);
            s += gk        * __ldg(&pr_W1[(64 + k) * 8 + j]);
            s += ik        * __ldg(&pr_W1[(128 + k) * 8 + j]);
        }
        sm[OFF_HPR + j] = fmaxf(s, 0.f);
    }
    __syncthreads();

    // ---------------- Phase 8: final outputs --------------------------------
    if (tid == 0) {
        g_dkl_partial[bid] = sm[OFF_RED + 8] + sm[OFF_RED + 9];
        float s = pr_b2[0];
        #pragma unroll
        for (int j = 0; j < 8; j++) s += sm[OFF_HPR + j] * pr_W2[j];
        y_out[bid] = 1.0f / (1.0f + __expf(-s));
    }
}

// Deterministic final reduction for dkl (fixed summation order).
extern "C" __global__ void __launch_bounds__(256)
reduce_dkl_kernel(float* __restrict__ out, int out_idx)
{
    __shared__ float red[256];
    float s = 0.f;
    for (int i = threadIdx.x; i < NB; i += 256) s += g_dkl_partial[i];
    red[threadIdx.x] = s;
    __syncthreads();
    for (int st = 128; st > 0; st >>= 1) {
        if (threadIdx.x < st) red[threadIdx.x] += red[threadIdx.x + st];
        __syncthreads();
    }
    if (threadIdx.x == 0) out[out_idx] = red[0] * (1.0f / (float)NB);
}

extern "C" void kernel_launch(void* const* d_in, const int* in_sizes, int n_in,
                              void* d_out, int out_size)
{
    cudaFuncSetAttribute(agree_kernel,
                         cudaFuncAttributeMaxDynamicSharedMemorySize, SMEM_BYTES);

    agree_kernel<<<NB, 256, SMEM_BYTES>>>(
        (const int*)d_in[0],   // group_inputs
        (const int*)d_in[1],   // item_inputs
        (const int*)d_in[2],   // group_members
        (const float*)d_in[3], // user_emb
        (const float*)d_in[4], // item_emb
        (const float*)d_in[5], // group_emb
        (const float*)d_in[6],  (const float*)d_in[7],   // ue_W1, ue_b1
        (const float*)d_in[8],  (const float*)d_in[9],   // ue_W2, ue_b2
        (const float*)d_in[10], (const float*)d_in[11],  // ge_W1, ge_b1
        (const float*)d_in[12], (const float*)d_in[13],  // ge_W2, ge_b2
        (const float*)d_in[14], (const float*)d_in[15],  // at_W1, at_b1
        (const float*)d_in[16], (const float*)d_in[17],  // at_W2, at_b2
        (const float*)d_in[18], (const float*)d_in[19],  // pr_W1, pr_b1
        (const float*)d_in[20], (const float*)d_in[21],  // pr_W2, pr_b2
        (float*)d_out);

    // y occupies [0, NB); dkl goes to the last element.
    reduce_dkl_kernel<<<1, 256>>>((float*)d_out, out_size - 1);
}